// round 8
// baseline (speedup 1.0000x reference)
#include <cuda_runtime.h>

#define N 8192
#define NMAT ((size_t)N * (size_t)N)          // 67108864
#define OFF_MASKS (4 * N * 3)                 // 98304
#define OFF_ADJ   (OFF_MASKS + 4 * N)         // 131072

// Voxel grids: dims = ceil(30/v)+1
// L1: vs(0.5,0.5,1.0) -> (61,61,31)
// L2: vs(0.7,0.7,1.2) -> (44,44,26)
// L3: vs(0.9,0.9,1.4) -> (35,35,23)
#define NSEG1 (61 * 61 * 31)   // 115351
#define NSEG2 (44 * 44 * 26)   // 50336
#define NSEG3 (35 * 35 * 23)   // 28175
#define NSEG_TOT (NSEG1 + NSEG2 + NSEG3)

#define FRONT_BLOCKS 128
#define FRONT_THREADS 192            // 128*192 = 24576 = N*3 (one per point-level)
#define TOTAL_BLOCKS (8 * 512 * 6)   // 24576
#define RESET_CHUNK 8                // 24576*8 >= NSEG_TOT

// Scratch zero-initialized at module load; distributed in-kernel reset restores
// it each run. g_first empty sentinel = 0 (we store N - i > 0).
__device__ float g_sx[NSEG_TOT];
__device__ float g_sy[NSEG_TOT];
__device__ float g_sz[NSEG_TOT];
__device__ float g_cn[NSEG_TOT];
__device__ int   g_first[NSEG_TOT];
__device__ float4 g_pts[4][N];            // (x,y,z,valid) per level
__device__ unsigned int g_bar;            // monotonic front barrier (never reset)
__device__ volatile unsigned int g_done;  // gather-complete counter (reset at run end)
__device__ unsigned int g_fin;            // block-retire counter   (reset at run end)

__constant__ int   c_la[6] = {0, 1, 2, 1, 2, 3};
__constant__ int   c_lb[6] = {1, 2, 3, 1, 2, 3};
__constant__ float c_r2[6] = {1.0f, 2.25f, 4.0f, 2.25f, 4.0f, 6.25f};

__device__ __forceinline__ int lin_index(int l, float x, float y, float z) {
    if (l == 0) {
        int ix = min(max((int)floorf(x / 0.5f), 0), 60);
        int iy = min(max((int)floorf(y / 0.5f), 0), 60);
        int iz = min(max((int)floorf(z / 1.0f), 0), 30);
        return (ix * 61 + iy) * 31 + iz;
    } else if (l == 1) {
        int ix = min(max((int)floorf(x / 0.7f), 0), 43);
        int iy = min(max((int)floorf(y / 0.7f), 0), 43);
        int iz = min(max((int)floorf(z / 1.2f), 0), 25);
        return NSEG1 + (ix * 44 + iy) * 26 + iz;
    } else {
        int ix = min(max((int)floorf(x / 0.9f), 0), 34);
        int iy = min(max((int)floorf(y / 0.9f), 0), 34);
        int iz = min(max((int)floorf(z / 1.4f), 0), 22);
        return NSEG1 + NSEG2 + (ix * 35 + iy) * 23 + iz;
    }
}

__device__ __forceinline__ float pairval(float4 a, float4 b, float r2) {
    float dx = a.x - b.x, dy = a.y - b.y, dz = a.z - b.z;
    float d2 = fmaf(dx, dx, fmaf(dy, dy, dz * dz));
    return (d2 <= r2) ? (a.w * b.w) : 0.0f;
}

// ONE kernel: blocks 0..127 run the voxel front (scatter -> barrier -> gather),
// publish via g_done; every block spin-waits on g_done, zeroes its scratch
// chunk (distributed reset for the next replay), then computes its adj tile.
// Front blocks are in dispatch wave 1 (bid-ordered), so spinning blocks can
// never starve them. Last retiring block resets the per-run counters.
__global__ void __launch_bounds__(256, 6) k_all(
        const float* __restrict__ pts, float* __restrict__ out) {
    const int t   = threadIdx.x;
    const int bid = blockIdx.x + 8 * (blockIdx.y + 512 * blockIdx.z);

    // ======== FRONT (blocks 0..127) ========
    if (bid < FRONT_BLOCKS) {
        int lin = -1, i = 0, l = 0;
        float x = 0.f, y = 0.f, z = 0.f;
        if (t < FRONT_THREADS) {
            const int g = bid * FRONT_THREADS + t;   // 0..24575
            l = g >> 13;                              // level 0..2
            i = g & (N - 1);                          // point 0..8191
            x = pts[i * 4 + 0];
            y = pts[i * 4 + 1];
            z = pts[i * 4 + 2];
            lin = lin_index(l, x, y, z);
            atomicAdd(&g_sx[lin], x);
            atomicAdd(&g_sy[lin], y);
            atomicAdd(&g_sz[lin], z);
            atomicAdd(&g_cn[lin], 1.0f);
            atomicMax(&g_first[lin], N - i);
        }
        __threadfence();
        __syncthreads();
        if (t == 0) {   // monotonic generation barrier among the 128 front blocks
            unsigned int old = atomicAdd(&g_bar, 1u);
            unsigned int target = (old / FRONT_BLOCKS + 1u) * FRONT_BLOCKS;
            while (*(volatile unsigned int*)&g_bar < target) { }
        }
        __syncthreads();
        __threadfence();

        if (t < FRONT_THREADS) {
            float c  = fmaxf(g_cn[lin], 1.0f);
            float rc = 1.0f / c;
            float cx = g_sx[lin] * rc;
            float cy = g_sy[lin] * rc;
            float cz = g_sz[lin] * rc;
            bool  m  = (g_first[lin] == N - i);
            float mf = m ? 1.0f : 0.0f;
            g_pts[l + 1][i] = make_float4(cx, cy, cz, mf);
            size_t co = (size_t)(l + 1) * (N * 3) + (size_t)i * 3;
            out[co + 0] = m ? cx : 0.0f;
            out[co + 1] = m ? cy : 0.0f;
            out[co + 2] = m ? cz : 0.0f;
            out[OFF_MASKS + (l + 1) * N + i] = mf;
            if (l == 0) {
                g_pts[0][i] = make_float4(x, y, z, 1.0f);
                out[i * 3 + 0] = x;
                out[i * 3 + 1] = y;
                out[i * 3 + 2] = z;
                out[OFF_MASKS + i] = 1.0f;
            }
        }
        __threadfence();
        __syncthreads();
        if (t == 0) atomicAdd((unsigned int*)&g_done, 1u);
    }

    // ======== WAIT for voxel data ========
    if (t == 0) {
        while (g_done < FRONT_BLOCKS) __nanosleep(64);
    }
    __syncthreads();
    __threadfence();

    // ======== distributed scratch reset (safe: all gathers done) ========
    if (t < RESET_CHUNK * 5) {
        int e = bid * RESET_CHUNK + (t & (RESET_CHUNK - 1));
        if (e < NSEG_TOT) {
            switch (t >> 3) {
                case 0: g_sx[e] = 0.0f; break;
                case 1: g_sy[e] = 0.0f; break;
                case 2: g_sz[e] = 0.0f; break;
                case 3: g_cn[e] = 0.0f; break;
                case 4: g_first[e] = 0; break;
            }
        }
    }

    // ======== ADJ tile (R1 config: 16 x 1024, float4 stores) ========
    {
        const int mat = blockIdx.z;
        __shared__ float4 sa[16];
        const int   la = c_la[mat];
        const int   lb = c_lb[mat];
        const float r2 = c_r2[mat];
        const bool  diag = (mat >= 3);

        const int i0 = blockIdx.y * 16;
        const int j0 = blockIdx.x * 1024;

        if (t < 16) sa[t] = g_pts[la][i0 + t];
        __syncthreads();

        const int j = j0 + t * 4;
        const float4 b0 = g_pts[lb][j + 0];
        const float4 b1 = g_pts[lb][j + 1];
        const float4 b2 = g_pts[lb][j + 2];
        const float4 b3 = g_pts[lb][j + 3];

        float* obase = out + OFF_ADJ + (size_t)mat * NMAT + (size_t)j;

#pragma unroll
        for (int ii = 0; ii < 16; ii++) {
            float4 a = sa[ii];
            int gi = i0 + ii;
            float4 v;
            v.x = pairval(a, b0, r2);
            v.y = pairval(a, b1, r2);
            v.z = pairval(a, b2, r2);
            v.w = pairval(a, b3, r2);
            if (diag) {
                int d = gi - j;
                if ((unsigned)d < 4u) ((float*)&v)[d] = 0.0f;
            }
            *(float4*)(obase + (size_t)gi * N) = v;
        }
    }

    // ======== run-end counter reset (last block only) ========
    __syncthreads();
    if (t == 0) {
        unsigned int old = atomicAdd(&g_fin, 1u);
        if (old == TOTAL_BLOCKS - 1) {
            g_done = 0u;                       // volatile store
            *(volatile unsigned int*)&g_fin = 0u;
            __threadfence();
        }
    }
}

extern "C" void kernel_launch(void* const* d_in, const int* in_sizes, int n_in,
                              void* d_out, int out_size) {
    const float* pts = (const float*)d_in[0];
    float* out = (float*)d_out;

    dim3 grid(8, 512, 6);
    k_all<<<grid, 256>>>(pts, out);
}

// round 10
// speedup vs baseline: 1.4278x; 1.4278x over previous
#include <cuda_runtime.h>

#define N 8192
#define NMAT ((size_t)N * (size_t)N)          // 67108864
#define OFF_MASKS (4 * N * 3)                 // 98304
#define OFF_ADJ   (OFF_MASKS + 4 * N)         // 131072

// Voxel grids: dims = ceil(30/v)+1
// L1: vs(0.5,0.5,1.0) -> (61,61,31)
// L2: vs(0.7,0.7,1.2) -> (44,44,26)
// L3: vs(0.9,0.9,1.4) -> (35,35,23)
#define NSEG1 (61 * 61 * 31)   // 115351
#define NSEG2 (44 * 44 * 26)   // 50336
#define NSEG3 (35 * 35 * 23)   // 28175
#define NSEG_TOT (NSEG1 + NSEG2 + NSEG3)

#define FRONT_BLOCKS 128
#define FRONT_THREADS 192      // 128*192 = 24576 = N*3 (one thread per point-level)
#define RESET_CHUNK 8          // 24576 adj blocks * 8 >= NSEG_TOT

// Scratch zero-initialized at module load; the adj kernel's tail (distributed,
// post-grid-dependency-sync, atomic-free) restores it for the next replay.
// g_first empty sentinel = 0 (we store N - i > 0; max(N-i) == N - min(i)).
__device__ float g_sx[NSEG_TOT];
__device__ float g_sy[NSEG_TOT];
__device__ float g_sz[NSEG_TOT];
__device__ float g_cn[NSEG_TOT];
__device__ int   g_first[NSEG_TOT];
__device__ float4 g_pts[4][N];          // (x,y,z,valid) per level
__device__ unsigned int g_bar;          // monotonic grid barrier (never reset)

__constant__ int   c_la[6] = {0, 1, 2, 1, 2, 3};
__constant__ int   c_lb[6] = {1, 2, 3, 1, 2, 3};
__constant__ float c_r2[6] = {1.0f, 2.25f, 4.0f, 2.25f, 4.0f, 6.25f};

__device__ __forceinline__ int lin_index(int l, float x, float y, float z) {
    if (l == 0) {
        int ix = min(max((int)floorf(x / 0.5f), 0), 60);
        int iy = min(max((int)floorf(y / 0.5f), 0), 60);
        int iz = min(max((int)floorf(z / 1.0f), 0), 30);
        return (ix * 61 + iy) * 31 + iz;
    } else if (l == 1) {
        int ix = min(max((int)floorf(x / 0.7f), 0), 43);
        int iy = min(max((int)floorf(y / 0.7f), 0), 43);
        int iz = min(max((int)floorf(z / 1.2f), 0), 25);
        return NSEG1 + (ix * 44 + iy) * 26 + iz;
    } else {
        int ix = min(max((int)floorf(x / 0.9f), 0), 34);
        int iy = min(max((int)floorf(y / 0.9f), 0), 34);
        int iz = min(max((int)floorf(z / 1.4f), 0), 22);
        return NSEG1 + NSEG2 + (ix * 35 + iy) * 23 + iz;
    }
}

// Fused scatter + grid-barrier + gather (R7 config, 9.5us measured). Triggers
// PDL at entry so the adjacency grid can dispatch concurrently; adj's
// grid-dependency sync still waits for this kernel's completion.
__global__ void __launch_bounds__(FRONT_THREADS) k_front(
        const float* __restrict__ pts, float* __restrict__ out) {
    cudaTriggerProgrammaticLaunchCompletion();

    const int g = blockIdx.x * FRONT_THREADS + threadIdx.x;   // 0..24575
    const int l = g >> 13;          // level 0..2 (warp-uniform)
    const int i = g & (N - 1);      // point 0..8191 (consecutive in warp)

    const float x = pts[i * 4 + 0];
    const float y = pts[i * 4 + 1];
    const float z = pts[i * 4 + 2];
    const int lin = lin_index(l, x, y, z);

    // ---- scatter (5 independent L2 red/atomics) ----
    atomicAdd(&g_sx[lin], x);
    atomicAdd(&g_sy[lin], y);
    atomicAdd(&g_sz[lin], z);
    atomicAdd(&g_cn[lin], 1.0f);
    atomicMax(&g_first[lin], N - i);

    // ---- grid-wide barrier (monotonic generation; 128 co-resident blocks) ----
    __threadfence();
    __syncthreads();
    if (threadIdx.x == 0) {
        unsigned int old = atomicAdd(&g_bar, 1u);
        unsigned int target = (old / FRONT_BLOCKS + 1u) * FRONT_BLOCKS;
        while (*(volatile unsigned int*)&g_bar < target) __nanosleep(32);
    }
    __syncthreads();
    __threadfence();

    // ---- gather for this (point, level) ----
    float c  = fmaxf(g_cn[lin], 1.0f);
    float rc = 1.0f / c;
    float cx = g_sx[lin] * rc;
    float cy = g_sy[lin] * rc;
    float cz = g_sz[lin] * rc;
    bool  m  = (g_first[lin] == N - i);
    float mf = m ? 1.0f : 0.0f;
    g_pts[l + 1][i] = make_float4(cx, cy, cz, mf);
    size_t co = (size_t)(l + 1) * (N * 3) + (size_t)i * 3;
    out[co + 0] = m ? cx : 0.0f;
    out[co + 1] = m ? cy : 0.0f;
    out[co + 2] = m ? cz : 0.0f;
    out[OFF_MASKS + (l + 1) * N + i] = mf;

    if (l == 0) {
        g_pts[0][i] = make_float4(x, y, z, 1.0f);
        out[i * 3 + 0] = x;
        out[i * 3 + 1] = y;
        out[i * 3 + 2] = z;
        out[OFF_MASKS + i] = 1.0f;
    }
}

__device__ __forceinline__ float pairval(float4 a, float4 b, float r2) {
    float dx = a.x - b.x, dy = a.y - b.y, dz = a.z - b.z;
    float d2 = fmaf(dx, dx, fmaf(dy, dy, dz * dz));
    return (d2 <= r2) ? (a.w * b.w) : 0.0f;
}

// 16 (i) x 1024 (j) tile per 256-thread block (R1 hot loop, unchanged —
// measured ~87% of HBM write spec). Launched with PDL when available:
// prelude overlaps k_front; grid-dependency sync gates the g_pts reads.
// Tail: distributed scratch reset (no atomics, 0.24% extra traffic).
__global__ void __launch_bounds__(256) k_adj(float* __restrict__ out) {
    const int mat = blockIdx.z;
    __shared__ float4 sa[16];
    const int   la = c_la[mat];
    const int   lb = c_lb[mat];
    const float r2 = c_r2[mat];
    const bool  diag = (mat >= 3);

    const int i0 = blockIdx.y * 16;
    const int j0 = blockIdx.x * 1024;
    const int t  = threadIdx.x;
    const int j  = j0 + t * 4;

    // Wait for k_front completion before touching g_pts. No-op if this grid
    // was launched without PDL (plain stream ordering already guarantees it).
    cudaGridDependencySynchronize();

    if (t < 16) sa[t] = g_pts[la][i0 + t];
    __syncthreads();

    const float4 b0 = g_pts[lb][j + 0];
    const float4 b1 = g_pts[lb][j + 1];
    const float4 b2 = g_pts[lb][j + 2];
    const float4 b3 = g_pts[lb][j + 3];

    float* obase = out + OFF_ADJ + (size_t)mat * NMAT + (size_t)j;

#pragma unroll
    for (int ii = 0; ii < 16; ii++) {
        float4 a = sa[ii];
        int gi = i0 + ii;
        float4 v;
        v.x = pairval(a, b0, r2);
        v.y = pairval(a, b1, r2);
        v.z = pairval(a, b2, r2);
        v.w = pairval(a, b3, r2);
        if (diag) {
            int d = gi - j;
            if ((unsigned)d < 4u) ((float*)&v)[d] = 0.0f;
        }
        *(float4*)(obase + (size_t)gi * N) = v;
    }

    // Distributed scratch reset for the next replay (front is done; safe).
    if (t < RESET_CHUNK * 5) {
        const int bid = blockIdx.x + 8 * (blockIdx.y + 512 * blockIdx.z);
        int e = bid * RESET_CHUNK + (t & (RESET_CHUNK - 1));
        if (e < NSEG_TOT) {
            switch (t >> 3) {
                case 0: g_sx[e] = 0.0f; break;
                case 1: g_sy[e] = 0.0f; break;
                case 2: g_sz[e] = 0.0f; break;
                case 3: g_cn[e] = 0.0f; break;
                case 4: g_first[e] = 0; break;
            }
        }
    }
}

extern "C" void kernel_launch(void* const* d_in, const int* in_sizes, int n_in,
                              void* d_out, int out_size) {
    const float* pts = (const float*)d_in[0];
    float* out = (float*)d_out;

    k_front<<<FRONT_BLOCKS, FRONT_THREADS>>>(pts, out);

    cudaLaunchConfig_t cfg = {};
    cfg.gridDim  = dim3(N / 1024, N / 16, 6);
    cfg.blockDim = dim3(256, 1, 1);
    cfg.stream   = 0;
    cudaLaunchAttribute attr[1];
    attr[0].id = cudaLaunchAttributeProgrammaticStreamSerialization;
    attr[0].val.programmaticStreamSerializationAllowed = 1;
    cfg.attrs    = attr;
    cfg.numAttrs = 1;
    cudaError_t err = cudaLaunchKernelEx(&cfg, k_adj, out);
    if (err != cudaSuccess) {
        // Environment rejected the PDL attribute (e.g., under capture):
        // identical semantics via plain stream-ordered launch.
        cudaGetLastError();  // clear sticky error
        dim3 grid(N / 1024, N / 16, 6);
        k_adj<<<grid, 256>>>(out);
    }
}

// round 11
// speedup vs baseline: 1.4518x; 1.0168x over previous
#include <cuda_runtime.h>

#define N 8192
#define NMAT ((size_t)N * (size_t)N)          // 67108864
#define OFF_MASKS (4 * N * 3)                 // 98304
#define OFF_ADJ   (OFF_MASKS + 4 * N)         // 131072

// Voxel grids: dims = ceil(30/v)+1
// L1: vs(0.5,0.5,1.0) -> (61,61,31)
// L2: vs(0.7,0.7,1.2) -> (44,44,26)
// L3: vs(0.9,0.9,1.4) -> (35,35,23)
#define NSEG1 (61 * 61 * 31)   // 115351
#define NSEG2 (44 * 44 * 26)   // 50336
#define NSEG3 (35 * 35 * 23)   // 28175
#define NSEG_TOT (NSEG1 + NSEG2 + NSEG3)

#define FRONT_BLOCKS 128
#define FRONT_THREADS 192      // 128*192 = 24576 = N*3 (one thread per point-level)

// Scratch zero-initialized at module load; k_reset (side stream, hidden under
// adj) restores it each run. g_first empty sentinel = 0 (we store N - i > 0).
__device__ float g_sx[NSEG_TOT];
__device__ float g_sy[NSEG_TOT];
__device__ float g_sz[NSEG_TOT];
__device__ float g_cn[NSEG_TOT];
__device__ int   g_first[NSEG_TOT];
__device__ float4 g_pts[4][N];          // (x,y,z,valid) per level
__device__ unsigned int g_bar;          // monotonic grid barrier (never reset)

__constant__ int   c_la[6] = {0, 1, 2, 1, 2, 3};
__constant__ int   c_lb[6] = {1, 2, 3, 1, 2, 3};
__constant__ float c_r2[6] = {1.0f, 2.25f, 4.0f, 2.25f, 4.0f, 6.25f};

__device__ __forceinline__ int lin_index(int l, float x, float y, float z) {
    if (l == 0) {
        int ix = min(max((int)floorf(x / 0.5f), 0), 60);
        int iy = min(max((int)floorf(y / 0.5f), 0), 60);
        int iz = min(max((int)floorf(z / 1.0f), 0), 30);
        return (ix * 61 + iy) * 31 + iz;
    } else if (l == 1) {
        int ix = min(max((int)floorf(x / 0.7f), 0), 43);
        int iy = min(max((int)floorf(y / 0.7f), 0), 43);
        int iz = min(max((int)floorf(z / 1.2f), 0), 25);
        return NSEG1 + (ix * 44 + iy) * 26 + iz;
    } else {
        int ix = min(max((int)floorf(x / 0.9f), 0), 34);
        int iy = min(max((int)floorf(y / 0.9f), 0), 34);
        int iz = min(max((int)floorf(z / 1.4f), 0), 22);
        return NSEG1 + NSEG2 + (ix * 35 + iy) * 23 + iz;
    }
}

// Slim front: scatter + barrier + gather writing ONLY g_pts (the adj input).
// All `out` coords/masks writes are deferred to k_out (hidden under adj).
// g_pts[0] (raw points) is written PRE-barrier — overlaps the barrier spin.
__global__ void __launch_bounds__(FRONT_THREADS) k_front(
        const float* __restrict__ pts) {
    const int g = blockIdx.x * FRONT_THREADS + threadIdx.x;   // 0..24575
    const int l = g >> 13;          // level 0..2 (warp-uniform)
    const int i = g & (N - 1);      // point 0..8191 (consecutive in warp)

    const float x = pts[i * 4 + 0];
    const float y = pts[i * 4 + 1];
    const float z = pts[i * 4 + 2];
    const int lin = lin_index(l, x, y, z);

    // ---- scatter (5 independent L2 red/atomics) ----
    atomicAdd(&g_sx[lin], x);
    atomicAdd(&g_sy[lin], y);
    atomicAdd(&g_sz[lin], z);
    atomicAdd(&g_cn[lin], 1.0f);
    atomicMax(&g_first[lin], N - i);

    // Level-0 table: independent of scatter; do before the barrier.
    if (l == 0) g_pts[0][i] = make_float4(x, y, z, 1.0f);

    // ---- grid-wide barrier (monotonic generation; 128 co-resident blocks) ----
    __threadfence();
    __syncthreads();
    if (threadIdx.x == 0) {
        unsigned int old = atomicAdd(&g_bar, 1u);
        unsigned int target = (old / FRONT_BLOCKS + 1u) * FRONT_BLOCKS;
        while (*(volatile unsigned int*)&g_bar < target) __nanosleep(32);
    }
    __syncthreads();
    __threadfence();

    // ---- minimal gather: one float4 store per thread ----
    float c  = fmaxf(g_cn[lin], 1.0f);
    float rc = 1.0f / c;
    float cx = g_sx[lin] * rc;
    float cy = g_sy[lin] * rc;
    float cz = g_sz[lin] * rc;
    float mf = (g_first[lin] == N - i) ? 1.0f : 0.0f;
    g_pts[l + 1][i] = make_float4(cx, cy, cz, mf);
}

// Writes coords_out + masks_out for all 4 levels from g_pts.
// Runs on the side stream, hidden under k_adj (which doesn't touch out[0..OFF_ADJ)).
__global__ void k_out(float* __restrict__ out) {
    int g = blockIdx.x * blockDim.x + threadIdx.x;   // 0..32767
    int lvl = g >> 13;          // 0..3
    int i   = g & (N - 1);
    float4 p = g_pts[lvl][i];
    float m = p.w;
    size_t co = (size_t)lvl * (N * 3) + (size_t)i * 3;
    out[co + 0] = p.x * m;      // masked coords (m is exactly 0 or 1)
    out[co + 1] = p.y * m;
    out[co + 2] = p.z * m;
    out[OFF_MASKS + lvl * N + i] = m;
}

// Coalesced zeroing of all voxel scratch; side stream, hidden under adj.
__global__ void k_reset() {
    int i = blockIdx.x * blockDim.x + threadIdx.x;
    if (i < NSEG_TOT) {
        g_sx[i] = 0.0f; g_sy[i] = 0.0f; g_sz[i] = 0.0f; g_cn[i] = 0.0f;
        g_first[i] = 0;
    }
}

__device__ __forceinline__ float pairval(float4 a, float4 b, float r2) {
    float dx = a.x - b.x, dy = a.y - b.y, dz = a.z - b.z;
    float d2 = fmaf(dx, dx, fmaf(dy, dy, dz * dz));
    return (d2 <= r2) ? (a.w * b.w) : 0.0f;
}

// 16 (i) x 1024 (j) tile per 256-thread block; 4 j's per thread (float4 store).
// R1 configuration — measured ~87% of HBM spec, write-ceiling bound.
__global__ void __launch_bounds__(256) k_adj(float* __restrict__ out) {
    const int mat = blockIdx.z;
    __shared__ float4 sa[16];
    const int   la = c_la[mat];
    const int   lb = c_lb[mat];
    const float r2 = c_r2[mat];
    const bool  diag = (mat >= 3);

    const int i0 = blockIdx.y * 16;
    const int j0 = blockIdx.x * 1024;
    const int t  = threadIdx.x;

    if (t < 16) sa[t] = g_pts[la][i0 + t];
    __syncthreads();

    const int j = j0 + t * 4;
    const float4 b0 = g_pts[lb][j + 0];
    const float4 b1 = g_pts[lb][j + 1];
    const float4 b2 = g_pts[lb][j + 2];
    const float4 b3 = g_pts[lb][j + 3];

    float* obase = out + OFF_ADJ + (size_t)mat * NMAT + (size_t)j;

#pragma unroll
    for (int ii = 0; ii < 16; ii++) {
        float4 a = sa[ii];
        int gi = i0 + ii;
        float4 v;
        v.x = pairval(a, b0, r2);
        v.y = pairval(a, b1, r2);
        v.z = pairval(a, b2, r2);
        v.w = pairval(a, b3, r2);
        if (diag) {
            int d = gi - j;
            if ((unsigned)d < 4u) ((float*)&v)[d] = 0.0f;
        }
        *(float4*)(obase + (size_t)gi * N) = v;
    }
}

extern "C" void kernel_launch(void* const* d_in, const int* in_sizes, int n_in,
                              void* d_out, int out_size) {
    const float* pts = (const float*)d_in[0];
    float* out = (float*)d_out;

    // One-time side resources (resource init only; per-call work identical).
    static cudaStream_t s_side = nullptr;
    static cudaEvent_t  e_front = nullptr, e_side = nullptr;
    if (s_side == nullptr) {
        cudaStreamCreateWithFlags(&s_side, cudaStreamNonBlocking);
        cudaEventCreateWithFlags(&e_front, cudaEventDisableTiming);
        cudaEventCreateWithFlags(&e_side,  cudaEventDisableTiming);
    }

    // Critical path: slim front -> adj.
    k_front<<<FRONT_BLOCKS, FRONT_THREADS>>>(pts);
    cudaEventRecord(e_front, 0);

    // Side branch (hidden under adj): small outputs + scratch reset.
    cudaStreamWaitEvent(s_side, e_front, 0);
    k_out<<<(4 * N + 127) / 128, 128, 0, s_side>>>(out);
    k_reset<<<(NSEG_TOT + 255) / 256, 256, 0, s_side>>>();
    cudaEventRecord(e_side, s_side);

    dim3 grid(N / 1024, N / 16, 6);
    k_adj<<<grid, 256>>>(out);

    // Join.
    cudaStreamWaitEvent(0, e_side, 0);
}

// round 13
// speedup vs baseline: 1.4520x; 1.0001x over previous
#include <cuda_runtime.h>

#define N 8192
#define NMAT ((size_t)N * (size_t)N)          // 67108864
#define OFF_MASKS (4 * N * 3)                 // 98304
#define OFF_ADJ   (OFF_MASKS + 4 * N)         // 131072

// Voxel grids: dims = ceil(30/v)+1
// L1: vs(0.5,0.5,1.0) -> (61,61,31)
// L2: vs(0.7,0.7,1.2) -> (44,44,26)
// L3: vs(0.9,0.9,1.4) -> (35,35,23)
#define NSEG1 (61 * 61 * 31)   // 115351
#define NSEG2 (44 * 44 * 26)   // 50336
#define NSEG3 (35 * 35 * 23)   // 28175
#define NSEG_TOT (NSEG1 + NSEG2 + NSEG3)

#define FRONT_BLOCKS 128
#define FRONT_THREADS 192      // 128*192 = 24576 = N*3 (one thread per point-level)

// Scratch zero-initialized at module load; k_reset (side stream, hidden under
// adj) restores it each run. Sums interleaved as float4 {sx,sy,sz,cnt} so
// scatter hits ONE L2 sector and gather is a single 128-bit L2 load.
// g_first empty sentinel = 0 (we store N - i > 0; max(N-i) == N - min(i)).
__device__ float4 g_s4[NSEG_TOT];
__device__ int    g_first[NSEG_TOT];
__device__ float4 g_pts[4][N];          // (x,y,z,valid) per level
__device__ unsigned int g_bar;          // monotonic grid barrier (never reset)

__constant__ int   c_la[6] = {0, 1, 2, 1, 2, 3};
__constant__ int   c_lb[6] = {1, 2, 3, 1, 2, 3};
__constant__ float c_r2[6] = {1.0f, 2.25f, 4.0f, 2.25f, 4.0f, 6.25f};

__device__ __forceinline__ int lin_index(int l, float x, float y, float z) {
    if (l == 0) {
        int ix = min(max((int)floorf(x / 0.5f), 0), 60);
        int iy = min(max((int)floorf(y / 0.5f), 0), 60);
        int iz = min(max((int)floorf(z / 1.0f), 0), 30);
        return (ix * 61 + iy) * 31 + iz;
    } else if (l == 1) {
        int ix = min(max((int)floorf(x / 0.7f), 0), 43);
        int iy = min(max((int)floorf(y / 0.7f), 0), 43);
        int iz = min(max((int)floorf(z / 1.2f), 0), 25);
        return NSEG1 + (ix * 44 + iy) * 26 + iz;
    } else {
        int ix = min(max((int)floorf(x / 0.9f), 0), 34);
        int iy = min(max((int)floorf(y / 0.9f), 0), 34);
        int iz = min(max((int)floorf(z / 1.4f), 0), 22);
        return NSEG1 + NSEG2 + (ix * 35 + iy) * 23 + iz;
    }
}

// Slim front: scatter + barrier + minimal gather writing ONLY g_pts.
// Output coords/masks deferred to k_out (hidden under adj).
__global__ void __launch_bounds__(FRONT_THREADS) k_front(
        const float4* __restrict__ pts4) {
    const int g = blockIdx.x * FRONT_THREADS + threadIdx.x;   // 0..24575
    const int l = g >> 13;          // level 0..2 (warp-uniform)
    const int i = g & (N - 1);      // point 0..8191 (consecutive in warp)

    const float4 p = pts4[i];       // one LDG.128
    const float x = p.x, y = p.y, z = p.z;
    const int lin = lin_index(l, x, y, z);

    // ---- scatter: 4 atomics into one 16B sector + 1 atomicMax ----
    atomicAdd(&g_s4[lin].x, x);
    atomicAdd(&g_s4[lin].y, y);
    atomicAdd(&g_s4[lin].z, z);
    atomicAdd(&g_s4[lin].w, 1.0f);
    atomicMax(&g_first[lin], N - i);

    // Level-0 table: independent of scatter; overlaps the barrier.
    if (l == 0) g_pts[0][i] = make_float4(x, y, z, 1.0f);

    // ---- grid-wide barrier (monotonic generation; 128 co-resident blocks) ----
    __threadfence();
    __syncthreads();
    if (threadIdx.x == 0) {
        unsigned int old = atomicAdd(&g_bar, 1u);
        unsigned int target = (old / FRONT_BLOCKS + 1u) * FRONT_BLOCKS;
        while (*(volatile unsigned int*)&g_bar < target) __nanosleep(32);
    }
    __syncthreads();
    __threadfence();

    // ---- minimal gather: one L2 LDG.128 + one scalar, one STG.128 ----
    float4 s = __ldcg(&g_s4[lin]);      // .cg: L2-coherent, bypasses L1
    float rc = 1.0f / fmaxf(s.w, 1.0f);
    float mf = (__ldcg(&g_first[lin]) == N - i) ? 1.0f : 0.0f;
    g_pts[l + 1][i] = make_float4(s.x * rc, s.y * rc, s.z * rc, mf);
}

// Writes coords_out + masks_out for all 4 levels from g_pts.
// Side stream, hidden under k_adj (adj doesn't touch out[0..OFF_ADJ)).
__global__ void k_out(float* __restrict__ out) {
    int g = blockIdx.x * blockDim.x + threadIdx.x;   // 0..32767
    int lvl = g >> 13;          // 0..3
    int i   = g & (N - 1);
    float4 p = g_pts[lvl][i];
    float m = p.w;
    size_t co = (size_t)lvl * (N * 3) + (size_t)i * 3;
    out[co + 0] = p.x * m;      // masked coords (m is exactly 0 or 1)
    out[co + 1] = p.y * m;
    out[co + 2] = p.z * m;
    out[OFF_MASKS + lvl * N + i] = m;
}

// Coalesced zeroing of all voxel scratch; side stream, hidden under adj.
__global__ void k_reset() {
    int i = blockIdx.x * blockDim.x + threadIdx.x;
    if (i < NSEG_TOT) {
        g_s4[i] = make_float4(0.0f, 0.0f, 0.0f, 0.0f);
        g_first[i] = 0;
    }
}

__device__ __forceinline__ float pairval(float4 a, float4 b, float r2) {
    float dx = a.x - b.x, dy = a.y - b.y, dz = a.z - b.z;
    float d2 = fmaf(dx, dx, fmaf(dy, dy, dz * dz));
    return (d2 <= r2) ? (a.w * b.w) : 0.0f;
}

// 16 (i) x 1024 (j) tile per 256-thread block; 4 j's per thread (float4 store).
// R1 configuration — measured ~87% of HBM spec, write-ceiling bound.
__global__ void __launch_bounds__(256) k_adj(float* __restrict__ out) {
    const int mat = blockIdx.z;
    __shared__ float4 sa[16];
    const int   la = c_la[mat];
    const int   lb = c_lb[mat];
    const float r2 = c_r2[mat];
    const bool  diag = (mat >= 3);

    const int i0 = blockIdx.y * 16;
    const int j0 = blockIdx.x * 1024;
    const int t  = threadIdx.x;

    if (t < 16) sa[t] = g_pts[la][i0 + t];
    __syncthreads();

    const int j = j0 + t * 4;
    const float4 b0 = g_pts[lb][j + 0];
    const float4 b1 = g_pts[lb][j + 1];
    const float4 b2 = g_pts[lb][j + 2];
    const float4 b3 = g_pts[lb][j + 3];

    float* obase = out + OFF_ADJ + (size_t)mat * NMAT + (size_t)j;

#pragma unroll
    for (int ii = 0; ii < 16; ii++) {
        float4 a = sa[ii];
        int gi = i0 + ii;
        float4 v;
        v.x = pairval(a, b0, r2);
        v.y = pairval(a, b1, r2);
        v.z = pairval(a, b2, r2);
        v.w = pairval(a, b3, r2);
        if (diag) {
            int d = gi - j;
            if ((unsigned)d < 4u) ((float*)&v)[d] = 0.0f;
        }
        *(float4*)(obase + (size_t)gi * N) = v;
    }
}

extern "C" void kernel_launch(void* const* d_in, const int* in_sizes, int n_in,
                              void* d_out, int out_size) {
    const float4* pts4 = (const float4*)d_in[0];
    float* out = (float*)d_out;

    // One-time side resources (resource init only; per-call work identical).
    static cudaStream_t s_side = nullptr;
    static cudaEvent_t  e_front = nullptr, e_side = nullptr;
    if (s_side == nullptr) {
        cudaStreamCreateWithFlags(&s_side, cudaStreamNonBlocking);
        cudaEventCreateWithFlags(&e_front, cudaEventDisableTiming);
        cudaEventCreateWithFlags(&e_side,  cudaEventDisableTiming);
    }

    // Critical path: slim front -> adj.
    k_front<<<FRONT_BLOCKS, FRONT_THREADS>>>(pts4);
    cudaEventRecord(e_front, 0);

    // Side branch (hidden under adj): small outputs + scratch reset.
    cudaStreamWaitEvent(s_side, e_front, 0);
    k_out<<<(4 * N + 127) / 128, 128, 0, s_side>>>(out);
    k_reset<<<(NSEG_TOT + 255) / 256, 256, 0, s_side>>>();
    cudaEventRecord(e_side, s_side);

    dim3 grid(N / 1024, N / 16, 6);
    k_adj<<<grid, 256>>>(out);

    // Join.
    cudaStreamWaitEvent(0, e_side, 0);
}